// round 1
// baseline (speedup 1.0000x reference)
#include <cuda_runtime.h>
#include <math.h>
#include <float.h>

#define BB 32
#define NN 1024
#define BNTOT (BB * NN) /* 32768 */

// ---------------- scratch layout (floats) ----------------
static constexpr size_t CH      = (size_t)BB * NN;            // 32768 per channel
static constexpr size_t OFF_H1  = 0;
static constexpr size_t OFF_H2  = OFF_H1 + 64 * CH;
static constexpr size_t OFF_H3  = OFF_H2 + 64 * CH;
static constexpr size_t OFF_H4  = OFF_H3 + 64 * CH;
static constexpr size_t OFF_H5  = OFF_H4 + 128 * CH;
static constexpr size_t OFF_H6  = OFF_H5 + 1024 * CH;
static constexpr size_t OFF_H7  = OFF_H6 + 512 * CH;
static constexpr size_t OFF_H8  = OFF_H7 + 256 * CH;
static constexpr size_t OFF_H9  = OFF_H8 + 128 * CH;
static constexpr size_t OFF_MEAN  = OFF_H9 + 128 * CH;
static constexpr size_t OFF_RSTD  = OFF_MEAN + 10 * 1024;
static constexpr size_t OFF_GF    = OFF_RSTD + 10 * 1024;     // 32*1024 bn'd max
static constexpr size_t OFF_BIAS6 = OFF_GF + (size_t)BB * 1024; // 32*512
static constexpr size_t TOTAL_F   = OFF_BIAS6 + (size_t)BB * 512;

__device__ float g_buf[TOTAL_F];

// ---------------- Jacobi(a=1,b=1,deg=3) feature helper ----------------
__device__ __forceinline__ void jacobi4(float t, float& p0, float& p1, float& p2, float& p3)
{
    p0 = 1.0f;
    p1 = 2.0f * t;                        // (a-b + (a+b+2)t)/2
    p2 = 3.75f * t * t - 0.75f;           // 1.875*t*p1 - 0.75*p0
    p3 = 1.8666666666666667f * t * p2 - 0.8f * p1;
}

// ---------------- fused BN->tanh->Jacobi->GEMM layer ----------------
// Hin: (B, Cin, N) raw; mean/rstd: per-channel BN of Hin (nullptr = no BN);
// W: (Cin, Cout, 4); bias: (B, Cout) or nullptr; Hout: (B, Cout, N) raw.
__global__ __launch_bounds__(256) void kan_gemm(
    const float* __restrict__ Hin, const float* __restrict__ mean,
    const float* __restrict__ rstd, const float* __restrict__ W,
    const float* __restrict__ bias, float* __restrict__ Hout,
    int Cin, int Cout)
{
    __shared__ float Fs[64][64];   // feature f (=4*ic+d) x point n
    __shared__ float Ws[64][64];   // feature f x output o

    const int b     = blockIdx.z;
    const int nBase = blockIdx.x * 64;
    const int oBase = blockIdx.y * 64;
    const int tid   = threadIdx.x;
    const int tx    = tid & 15;    // point group
    const int ty    = tid >> 4;    // output group

    float acc[4][4];
#pragma unroll
    for (int j = 0; j < 4; j++)
#pragma unroll
        for (int k = 0; k < 4; k++) acc[j][k] = 0.0f;

    const float* Hb = Hin + (size_t)b * Cin * NN;
    const int nChunks = (Cin + 15) >> 4;

    for (int kc = 0; kc < nChunks; kc++) {
        // ---- stage weights: 64 features x 64 outputs ----
#pragma unroll
        for (int l = 0; l < 16; l++) {
            int idx = tid + l * 256;
            int f = idx >> 6, o = idx & 63;
            int i = kc * 16 + (f >> 2);
            int d = f & 3;
            float wv = 0.0f;
            if (i < Cin && (oBase + o) < Cout)
                wv = W[((size_t)i * Cout + (oBase + o)) * 4 + d];
            Ws[f][o] = wv;
        }
        // ---- stage features: bn -> tanh -> jacobi ----
#pragma unroll
        for (int l = 0; l < 4; l++) {
            int idx = tid + l * 256;
            int ic = idx >> 6, n = idx & 63;
            int i = kc * 16 + ic;
            float p0 = 0.f, p1 = 0.f, p2 = 0.f, p3 = 0.f;
            if (i < Cin) {
                float v = Hb[(size_t)i * NN + nBase + n];
                if (mean) v = (v - mean[i]) * rstd[i];
                float t = tanhf(v);
                jacobi4(t, p0, p1, p2, p3);
            }
            Fs[ic * 4 + 0][n] = p0;
            Fs[ic * 4 + 1][n] = p1;
            Fs[ic * 4 + 2][n] = p2;
            Fs[ic * 4 + 3][n] = p3;
        }
        __syncthreads();

#pragma unroll 16
        for (int f = 0; f < 64; f++) {
            float4 wv = *(const float4*)(&Ws[f][ty << 2]);
            float4 fv = *(const float4*)(&Fs[f][tx << 2]);
            acc[0][0] += wv.x * fv.x; acc[0][1] += wv.x * fv.y;
            acc[0][2] += wv.x * fv.z; acc[0][3] += wv.x * fv.w;
            acc[1][0] += wv.y * fv.x; acc[1][1] += wv.y * fv.y;
            acc[1][2] += wv.y * fv.z; acc[1][3] += wv.y * fv.w;
            acc[2][0] += wv.z * fv.x; acc[2][1] += wv.z * fv.y;
            acc[2][2] += wv.z * fv.z; acc[2][3] += wv.z * fv.w;
            acc[3][0] += wv.w * fv.x; acc[3][1] += wv.w * fv.y;
            acc[3][2] += wv.w * fv.z; acc[3][3] += wv.w * fv.w;
        }
        __syncthreads();
    }

#pragma unroll
    for (int j = 0; j < 4; j++) {
        int o = oBase + (ty << 2) + j;
        if (o < Cout) {
            float bv = bias ? bias[b * Cout + o] : 0.0f;
            float* dst = Hout + ((size_t)b * Cout + o) * NN + nBase + (tx << 2);
            dst[0] = acc[j][0] + bv;
            dst[1] = acc[j][1] + bv;
            dst[2] = acc[j][2] + bv;
            dst[3] = acc[j][3] + bv;
        }
    }
}

// ---------------- per-channel BN stats over (B, N) ----------------
__global__ __launch_bounds__(256) void bn_stats(
    const float* __restrict__ H, float* __restrict__ mean,
    float* __restrict__ rstd, int C)
{
    const int c = blockIdx.x;
    float s = 0.f, s2 = 0.f;
    for (int idx = threadIdx.x; idx < BNTOT; idx += 256) {
        int b = idx >> 10, n = idx & 1023;
        float v = H[((size_t)b * C + c) * NN + n];
        s += v; s2 += v * v;
    }
    __shared__ float sh1[256], sh2[256];
    sh1[threadIdx.x] = s; sh2[threadIdx.x] = s2;
    __syncthreads();
    for (int off = 128; off; off >>= 1) {
        if (threadIdx.x < off) {
            sh1[threadIdx.x] += sh1[threadIdx.x + off];
            sh2[threadIdx.x] += sh2[threadIdx.x + off];
        }
        __syncthreads();
    }
    if (threadIdx.x == 0) {
        float m   = sh1[0] * (1.0f / BNTOT);
        float var = sh2[0] * (1.0f / BNTOT) - m * m;
        mean[c] = m;
        rstd[c] = rsqrtf(var + 1e-5f);
    }
}

// ---------------- max over N of raw h5, then apply h5's BN ----------------
__global__ __launch_bounds__(128) void maxpool_bn(
    const float* __restrict__ H, const float* __restrict__ mean,
    const float* __restrict__ rstd, float* __restrict__ gf)
{
    const int c = blockIdx.x, b = blockIdx.y;
    const float* p = H + ((size_t)b * 1024 + c) * NN;
    float m = -FLT_MAX;
    for (int n = threadIdx.x; n < NN; n += 128) m = fmaxf(m, p[n]);
    __shared__ float sh[128];
    sh[threadIdx.x] = m;
    __syncthreads();
    for (int off = 64; off; off >>= 1) {
        if (threadIdx.x < off)
            sh[threadIdx.x] = fmaxf(sh[threadIdx.x], sh[threadIdx.x + off]);
        __syncthreads();
    }
    if (threadIdx.x == 0) gf[b * 1024 + c] = (sh[0] - mean[c]) * rstd[c];
}

// ---------------- fold broadcast gf channels of layer-6 into a (B, 512) bias ----
__global__ __launch_bounds__(256) void bias6_kernel(
    const float* __restrict__ gf, const float* __restrict__ W6,
    float* __restrict__ bias6)
{
    const int b = blockIdx.y;
    const int o = blockIdx.x * 256 + threadIdx.x; // Cout = 512, grid.x = 2
    __shared__ float feat[4096];
    for (int idx = threadIdx.x; idx < 1024; idx += 256) {
        float t = tanhf(gf[b * 1024 + idx]);
        float p0, p1, p2, p3;
        jacobi4(t, p0, p1, p2, p3);
        feat[idx * 4 + 0] = p0;
        feat[idx * 4 + 1] = p1;
        feat[idx * 4 + 2] = p2;
        feat[idx * 4 + 3] = p3;
    }
    __syncthreads();
    float s = 0.f;
    for (int c = 0; c < 1024; c++) {
        float4 w4 = *(const float4*)(W6 + ((size_t)(64 + c) * 512 + o) * 4);
        s += feat[c * 4 + 0] * w4.x + feat[c * 4 + 1] * w4.y +
             feat[c * 4 + 2] * w4.z + feat[c * 4 + 3] * w4.w;
    }
    bias6[b * 512 + o] = s;
}

// ---------------- host orchestration ----------------
extern "C" void kernel_launch(void* const* d_in, const int* in_sizes, int n_in,
                              void* d_out, int out_size)
{
    (void)in_sizes; (void)n_in; (void)out_size;
    const float* x = (const float*)d_in[0];
    const float* w[10];
    for (int i = 0; i < 10; i++) w[i] = (const float*)d_in[1 + i];

    float* buf = nullptr;
    cudaGetSymbolAddress((void**)&buf, g_buf);

    float* h1 = buf + OFF_H1;
    float* h2 = buf + OFF_H2;
    float* h3 = buf + OFF_H3;
    float* h4 = buf + OFF_H4;
    float* h5 = buf + OFF_H5;
    float* h6 = buf + OFF_H6;
    float* h7 = buf + OFF_H7;
    float* h8 = buf + OFF_H8;
    float* h9 = buf + OFF_H9;
    float* meanB = buf + OFF_MEAN;
    float* rstdB = buf + OFF_RSTD;
    float* gf    = buf + OFF_GF;
    float* bias6 = buf + OFF_BIAS6;

    dim3 blk(256);
    auto kan = [&](const float* Hin, const float* m, const float* r,
                   const float* W, const float* bias, float* Hout,
                   int Cin, int Cout) {
        dim3 grid(NN / 64, (Cout + 63) / 64, BB);
        kan_gemm<<<grid, blk>>>(Hin, m, r, W, bias, Hout, Cin, Cout);
    };
    auto stats = [&](const float* H, int C, int slot) {
        bn_stats<<<C, 256>>>(H, meanB + slot * 1024, rstdB + slot * 1024, C);
    };
    auto M = [&](int slot) { return meanB + slot * 1024; };
    auto R = [&](int slot) { return rstdB + slot * 1024; };

    kan(x, nullptr, nullptr, w[0], nullptr, h1, 2, 64);
    stats(h1, 64, 0);
    kan(h1, M(0), R(0), w[1], nullptr, h2, 64, 64);
    stats(h2, 64, 1);
    kan(h2, M(1), R(1), w[2], nullptr, h3, 64, 64);
    stats(h3, 64, 2);
    kan(h3, M(2), R(2), w[3], nullptr, h4, 64, 128);
    stats(h4, 128, 3);
    kan(h4, M(3), R(3), w[4], nullptr, h5, 128, 1024);
    stats(h5, 1024, 4);

    {
        dim3 g(1024, BB);
        maxpool_bn<<<g, 128>>>(h5, M(4), R(4), gf);
    }
    {
        dim3 g(2, BB);
        bias6_kernel<<<g, 256>>>(gf, w[5], bias6);
    }

    // layer 6: local part uses h2 with its BN stats (= local_feature),
    // broadcast gf part folded into bias6. W6 rows 0..63 are the local rows.
    kan(h2, M(1), R(1), w[5], bias6, h6, 64, 512);
    stats(h6, 512, 5);
    kan(h6, M(5), R(5), w[6], nullptr, h7, 512, 256);
    stats(h7, 256, 6);
    kan(h7, M(6), R(6), w[7], nullptr, h8, 256, 128);
    stats(h8, 128, 7);
    kan(h8, M(7), R(7), w[8], nullptr, h9, 128, 128);
    stats(h9, 128, 8);
    kan(h9, M(8), R(8), w[9], nullptr, (float*)d_out, 128, 3);
}

// round 3
// speedup vs baseline: 2.2437x; 2.2437x over previous
#include <cuda_runtime.h>
#include <cuda_bf16.h>
#include <math.h>
#include <float.h>
#include <stdint.h>

#define BB 32
#define NN 1024
#define BN_TOT 32768
#define GX 256                     /* point tiles = BN/128 */

#define SWZ128(o) ((o) ^ (((o) >> 3) & 0x70))

__device__ __forceinline__ uint32_t smem_u32(const void* p) {
    uint32_t a;
    asm("{ .reg .u64 t; cvta.to.shared.u64 t, %1; cvt.u32.u64 %0, t; }"
        : "=r"(a) : "l"(p));
    return a;
}
__device__ __forceinline__ uint32_t pack_bf2(float lo, float hi) {
    uint32_t r;
    asm("cvt.rn.bf16x2.f32 %0, %1, %2;" : "=r"(r) : "f"(hi), "f"(lo));
    return r;
}
__device__ __forceinline__ void ldm_x4(uint32_t* r, uint32_t addr) {
    asm volatile("ldmatrix.sync.aligned.m8n8.x4.shared.b16 {%0,%1,%2,%3}, [%4];"
                 : "=r"(r[0]), "=r"(r[1]), "=r"(r[2]), "=r"(r[3]) : "r"(addr));
}
__device__ __forceinline__ void ldm_x2(uint32_t* r, uint32_t addr) {
    asm volatile("ldmatrix.sync.aligned.m8n8.x2.shared.b16 {%0,%1}, [%2];"
                 : "=r"(r[0]), "=r"(r[1]) : "r"(addr));
}
__device__ __forceinline__ void mma16816(float* d, const uint32_t* a, const uint32_t* b) {
    asm volatile(
        "mma.sync.aligned.m16n8k16.row.col.f32.bf16.bf16.f32 "
        "{%0,%1,%2,%3}, {%4,%5,%6,%7}, {%8,%9}, {%0,%1,%2,%3};"
        : "+f"(d[0]), "+f"(d[1]), "+f"(d[2]), "+f"(d[3])
        : "r"(a[0]), "r"(a[1]), "r"(a[2]), "r"(a[3]), "r"(b[0]), "r"(b[1]));
}

// ===================== scratch =====================
static constexpr size_t CH = (size_t)BN_TOT;
static constexpr size_t OFF_XT = 0;                    // 2 ch
static constexpr size_t OFF_H1 = OFF_XT + 2 * CH;
static constexpr size_t OFF_H2 = OFF_H1 + 64 * CH;
static constexpr size_t OFF_H3 = OFF_H2 + 64 * CH;
static constexpr size_t OFF_H4 = OFF_H3 + 64 * CH;
static constexpr size_t OFF_H6 = OFF_H4 + 128 * CH;    // h5 never materialized
static constexpr size_t OFF_H7 = OFF_H6 + 512 * CH;
static constexpr size_t OFF_H8 = OFF_H7 + 256 * CH;
static constexpr size_t OFF_H9 = OFF_H8 + 128 * CH;
static constexpr size_t OFF_MEAN = OFF_H9 + 128 * CH;  // 10*1024
static constexpr size_t OFF_RSTD = OFF_MEAN + 10 * 1024;
static constexpr size_t OFF_GF   = OFF_RSTD + 10 * 1024;       // 32*1024
static constexpr size_t OFF_B6   = OFF_GF + (size_t)BB * 1024; // 32*512
static constexpr size_t OFF_PS   = OFF_B6 + (size_t)BB * 512;  // 1024*GX
static constexpr size_t OFF_PQ   = OFF_PS + 1024 * (size_t)GX;
static constexpr size_t OFF_PM   = OFF_PQ + 1024 * (size_t)GX;
static constexpr size_t TOTAL_F  = OFF_PM + 1024 * (size_t)GX;

__device__ float g_buf[TOTAL_F];

static constexpr size_t WTOT = 1548288;
__device__ __nv_bfloat16 g_whi[WTOT];
__device__ __nv_bfloat16 g_wlo[WTOT];

// ===================== weight convert: fp32 (Cin,Cout,4) -> bf16 hi/lo [rows][Kp]
__global__ __launch_bounds__(256) void wcvt(
    const float* __restrict__ W, int Cout, int CinEff, int Kp, int rows,
    __nv_bfloat16* __restrict__ hi, __nv_bfloat16* __restrict__ lo)
{
    int idx = blockIdx.x * 256 + threadIdx.x;
    if (idx >= rows * Kp) return;
    int r = idx / Kp, k = idx - r * Kp;
    int i = k >> 2, d = k & 3;
    float w = 0.0f;
    if (r < Cout && i < CinEff)
        w = W[((size_t)i * Cout + r) * 4 + d];
    __nv_bfloat16 h = __float2bfloat16(w);
    hi[idx] = h;
    lo[idx] = __float2bfloat16(w - __bfloat162float(h));
}

// ===================== x (B,2,N) -> xT [2][B*N] =====================
__global__ __launch_bounds__(256) void xpose(const float* __restrict__ x,
                                             float* __restrict__ xT)
{
    int idx = blockIdx.x * 256 + threadIdx.x;
    if (idx >= 2 * BN_TOT) return;
    int c = idx >> 15, bn = idx & (BN_TOT - 1);
    int b = bn >> 10, n = bn & 1023;
    xT[idx] = x[((size_t)b * 2 + c) * NN + n];
}

// ===================== fused featurize + split-bf16 HMMA GEMM ==============
// SMEM: WH 16K | WL 16K | FH 16K | FL 16K  (tiles reused as reduce buffer)
static constexpr int S_WH = 0;
static constexpr int S_WL = 16384;
static constexpr int S_FH = 32768;
static constexpr int S_FL = 49152;
static constexpr int S_TOTAL = 65536;

__global__ __launch_bounds__(512) void kan_mma(
    const float* __restrict__ Hin, const float* __restrict__ mean,
    const float* __restrict__ rstd,
    const __nv_bfloat16* __restrict__ Whi, const __nv_bfloat16* __restrict__ Wlo,
    const float* __restrict__ bias, float* __restrict__ out,
    float* __restrict__ psum, float* __restrict__ pq, float* __restrict__ pmax,
    int Cin, int Cout, int Kp, int nChunks,
    int writeMode /*0 normal,1 final(B,3,N),2 none*/, int doStats, int doMax)
{
    extern __shared__ __align__(1024) char dsm[];
    const uint32_t sb = smem_u32(dsm);
    const int tid = threadIdx.x;
    const int wid = tid >> 5;
    const int lane = tid & 31;
    const int warpM = wid >> 2;   // 0..3 (32 out rows each)
    const int warpN = wid & 3;    // 0..3 (32 points each)
    const int pBase = blockIdx.x * 128;
    const int oBase = blockIdx.y * 128;
    const bool hasBN = (mean != nullptr);

    float acc[2][4][4];
#pragma unroll
    for (int mt = 0; mt < 2; mt++)
#pragma unroll
        for (int nt = 0; nt < 4; nt++)
#pragma unroll
            for (int e = 0; e < 4; e++) acc[mt][nt][e] = 0.0f;

    const int icl = tid >> 5;     // feature channel (0..15)
    const int pl  = tid & 31;     // point sub-index

    for (int kc = 0; kc < nChunks; kc++) {
        // ---- produce features: 16 channels x 128 points ----
        {
            const int ch = kc * 16 + icl;
            const bool valid = ch < Cin;
            float mn = 0.f, rs = 1.f;
            if (hasBN && valid) { mn = mean[ch]; rs = rstd[ch]; }
            const float* hrow = Hin + (size_t)(valid ? ch : 0) * BN_TOT + pBase;
#pragma unroll
            for (int j = 0; j < 4; j++) {
                const int p = pl + 32 * j;
                float xv = valid ? hrow[p] : 0.f;
                float v = hasBN ? (xv - mn) * rs : xv;
                float t = tanhf(v);
                float q1 = 2.0f * t;
                float q2 = 3.75f * t * t - 0.75f;
                float q3 = 1.8666666666666667f * t * q2 - 0.8f * q1;
                uint32_t w01 = pack_bf2(1.0f, q1);
                uint32_t w23 = pack_bf2(q2, q3);
                float h1f = __uint_as_float(w01 & 0xFFFF0000u);
                float h2f = __uint_as_float(w23 << 16);
                float h3f = __uint_as_float(w23 & 0xFFFF0000u);
                uint32_t l01 = pack_bf2(0.0f, q1 - h1f);
                uint32_t l23 = pack_bf2(q2 - h2f, q3 - h3f);
                int o0 = SWZ128(p * 128 + icl * 8);
                *(uint32_t*)(dsm + S_FH + o0)     = w01;
                *(uint32_t*)(dsm + S_FH + o0 + 4) = w23;
                *(uint32_t*)(dsm + S_FL + o0)     = l01;
                *(uint32_t*)(dsm + S_FL + o0 + 4) = l23;
            }
        }
        // ---- stage weight tiles ----
        {
#pragma unroll
            for (int l = 0; l < 8; l++) {
                int idx = tid + l * 512;
                int row = idx >> 5, c4 = idx & 31;
                size_t g = (size_t)(oBase + row) * Kp + (size_t)kc * 64 + c4 * 2;
                uint32_t vh = *(const uint32_t*)(Whi + g);
                uint32_t vl = *(const uint32_t*)(Wlo + g);
                int off = SWZ128(row * 128 + c4 * 4);
                *(uint32_t*)(dsm + S_WH + off) = vh;
                *(uint32_t*)(dsm + S_WL + off) = vl;
            }
        }
        __syncthreads();

        // ---- consume: 4 k16 steps, 3 split parts ----
#pragma unroll
        for (int ks = 0; ks < 4; ks++) {
            uint32_t ah[2][4], al[2][4];
#pragma unroll
            for (int mt = 0; mt < 2; mt++) {
                int r = warpM * 32 + mt * 16 + (lane & 15);
                int cB = ks * 32 + (lane >> 4) * 16;
                uint32_t a = sb + SWZ128(r * 128 + cB);
                ldm_x4(ah[mt], a + S_WH);
                ldm_x4(al[mt], a + S_WL);
            }
            uint32_t fh[4][2], fl[4][2];
#pragma unroll
            for (int nt = 0; nt < 4; nt++) {
                int rN = warpN * 32 + nt * 8 + (lane & 7);
                int cB = ks * 32 + ((lane >> 3) & 1) * 16;
                uint32_t a = sb + SWZ128(rN * 128 + cB);
                ldm_x2(fh[nt], a + S_FH);
                ldm_x2(fl[nt], a + S_FL);
            }
#pragma unroll
            for (int mt = 0; mt < 2; mt++)
#pragma unroll
                for (int nt = 0; nt < 4; nt++) {
                    mma16816(acc[mt][nt], ah[mt], fh[nt]);
                    mma16816(acc[mt][nt], al[mt], fh[nt]);
                    mma16816(acc[mt][nt], ah[mt], fl[nt]);
                }
        }
        __syncthreads();
    }

    // ---- epilogue ----
    const int bIdx = pBase >> 10;

    // bias (per output row, constant over the tile's points)
#pragma unroll
    for (int mt = 0; mt < 2; mt++)
#pragma unroll
        for (int h = 0; h < 2; h++) {
            int o = oBase + warpM * 32 + mt * 16 + h * 8 + (lane >> 2);
            float bv = 0.f;
            if (bias && o < Cout) bv = bias[bIdx * Cout + o];
            if (bv != 0.f)
#pragma unroll
                for (int nt = 0; nt < 4; nt++) {
                    acc[mt][nt][h * 2 + 0] += bv;
                    acc[mt][nt][h * 2 + 1] += bv;
                }
        }

    if (writeMode == 0) {
#pragma unroll
        for (int mt = 0; mt < 2; mt++)
#pragma unroll
            for (int h = 0; h < 2; h++) {
                int o = oBase + warpM * 32 + mt * 16 + h * 8 + (lane >> 2);
                if (o < Cout) {
                    float* rowp = out + (size_t)o * BN_TOT + pBase;
#pragma unroll
                    for (int nt = 0; nt < 4; nt++) {
                        int p = warpN * 32 + nt * 8 + (lane & 3) * 2;
                        float2 v = make_float2(acc[mt][nt][h * 2], acc[mt][nt][h * 2 + 1]);
                        *(float2*)(rowp + p) = v;
                    }
                }
            }
    } else if (writeMode == 1) {
#pragma unroll
        for (int mt = 0; mt < 2; mt++)
#pragma unroll
            for (int h = 0; h < 2; h++) {
                int o = oBase + warpM * 32 + mt * 16 + h * 8 + (lane >> 2);
                if (o < 3) {
                    float* rowp = out + ((size_t)bIdx * 3 + o) * 1024 + (pBase & 1023);
#pragma unroll
                    for (int nt = 0; nt < 4; nt++) {
                        int p = warpN * 32 + nt * 8 + (lane & 3) * 2;
                        rowp[p]     = acc[mt][nt][h * 2];
                        rowp[p + 1] = acc[mt][nt][h * 2 + 1];
                    }
                }
            }
    }

    if (doStats) {
        float* red = (float*)dsm;   // tiles are dead; reuse
#pragma unroll
        for (int mt = 0; mt < 2; mt++)
#pragma unroll
            for (int h = 0; h < 2; h++) {
                float s = 0.f, q = 0.f, mx = -FLT_MAX;
#pragma unroll
                for (int nt = 0; nt < 4; nt++)
#pragma unroll
                    for (int e = 0; e < 2; e++) {
                        float v = acc[mt][nt][h * 2 + e];
                        s += v; q += v * v; mx = fmaxf(mx, v);
                    }
                s += __shfl_xor_sync(~0u, s, 1); s += __shfl_xor_sync(~0u, s, 2);
                q += __shfl_xor_sync(~0u, q, 1); q += __shfl_xor_sync(~0u, q, 2);
                mx = fmaxf(mx, __shfl_xor_sync(~0u, mx, 1));
                mx = fmaxf(mx, __shfl_xor_sync(~0u, mx, 2));
                if ((lane & 3) == 0) {
                    int row = warpM * 32 + mt * 16 + h * 8 + (lane >> 2);
                    red[warpN * 128 + row] = s;
                    red[512 + warpN * 128 + row] = q;
                    if (doMax) red[1024 + warpN * 128 + row] = mx;
                }
            }
        __syncthreads();
        if (tid < 128) {
            float s = 0.f, q = 0.f, mx = -FLT_MAX;
#pragma unroll
            for (int wn = 0; wn < 4; wn++) {
                s += red[wn * 128 + tid];
                q += red[512 + wn * 128 + tid];
                if (doMax) mx = fmaxf(mx, red[1024 + wn * 128 + tid]);
            }
            int o = oBase + tid;
            psum[(size_t)o * GX + blockIdx.x] = s;
            pq[(size_t)o * GX + blockIdx.x] = q;
            if (doMax) pmax[(size_t)o * GX + blockIdx.x] = mx;
        }
    }
}

// ===================== BN finalize: warp per channel =====================
__global__ __launch_bounds__(256) void bn_fin(
    const float* __restrict__ ps, const float* __restrict__ pq,
    float* __restrict__ mean, float* __restrict__ rstd, int C)
{
    int w = threadIdx.x >> 5, lane = threadIdx.x & 31;
    int c = blockIdx.x * 8 + w;
    if (c >= C) return;
    float s = 0.f, q = 0.f;
    for (int j = lane; j < GX; j += 32) {
        s += ps[(size_t)c * GX + j];
        q += pq[(size_t)c * GX + j];
    }
#pragma unroll
    for (int o = 16; o; o >>= 1) {
        s += __shfl_xor_sync(~0u, s, o);
        q += __shfl_xor_sync(~0u, q, o);
    }
    if (lane == 0) {
        float m = s * (1.0f / BN_TOT);
        mean[c] = m;
        rstd[c] = rsqrtf(q * (1.0f / BN_TOT) - m * m + 1e-5f);
    }
}

// ===================== gf finalize: max over 8 point-tiles, then BN =========
__global__ __launch_bounds__(256) void gf_fin(
    const float* __restrict__ pm, const float* __restrict__ mean,
    const float* __restrict__ rstd, float* __restrict__ gf)
{
    int c = blockIdx.x * 256 + threadIdx.x;   // 0..1023, grid.x = 4
    int b = blockIdx.y;
    float mx = -FLT_MAX;
#pragma unroll
    for (int j = 0; j < 8; j++)
        mx = fmaxf(mx, pm[(size_t)c * GX + b * 8 + j]);
    gf[b * 1024 + c] = (mx - mean[c]) * rstd[c];
}

// ===================== fold broadcast gf channels into layer-6 bias ==========
__global__ __launch_bounds__(256) void bias6_kernel(const float* __restrict__ gf,
                                                    const float* __restrict__ W6,
                                                    float* __restrict__ bias6)
{
    const int b = blockIdx.y;
    const int o = blockIdx.x * 256 + threadIdx.x;
    __shared__ float feat[4096];
    for (int idx = threadIdx.x; idx < 1024; idx += 256) {
        float t = tanhf(gf[b * 1024 + idx]);
        float q1 = 2.0f * t;
        float q2 = 3.75f * t * t - 0.75f;
        float q3 = 1.8666666666666667f * t * q2 - 0.8f * q1;
        feat[idx * 4 + 0] = 1.0f;
        feat[idx * 4 + 1] = q1;
        feat[idx * 4 + 2] = q2;
        feat[idx * 4 + 3] = q3;
    }
    __syncthreads();
    float s = 0.f;
    for (int c = 0; c < 1024; c++) {
        float4 w4 = *(const float4*)(W6 + ((size_t)(64 + c) * 512 + o) * 4);
        s += feat[c * 4 + 0] * w4.x + feat[c * 4 + 1] * w4.y +
             feat[c * 4 + 2] * w4.z + feat[c * 4 + 3] * w4.w;
    }
    bias6[b * 512 + o] = s;
}

// ===================== host =====================
struct LayerP { int cin, cout, kp, rows; size_t woff; };

extern "C" void kernel_launch(void* const* d_in, const int* in_sizes, int n_in,
                              void* d_out, int out_size)
{
    (void)in_sizes; (void)n_in; (void)out_size;
    const float* x = (const float*)d_in[0];
    const float* w[10];
    for (int i = 0; i < 10; i++) w[i] = (const float*)d_in[1 + i];

    float* buf = nullptr;
    cudaGetSymbolAddress((void**)&buf, g_buf);
    __nv_bfloat16* whi = nullptr;
    __nv_bfloat16* wlo = nullptr;
    cudaGetSymbolAddress((void**)&whi, g_whi);
    cudaGetSymbolAddress((void**)&wlo, g_wlo);

    static const LayerP L[10] = {
        {  2,   64,   64,  128,       0},
        { 64,   64,  256,  128,    8192},
        { 64,   64,  256,  128,   40960},
        { 64,  128,  256,  128,   73728},
        {128, 1024,  512, 1024,  106496},
        { 64,  512,  256,  512,  630784},
        {512,  256, 2048,  256,  761856},
        {256,  128, 1024,  128, 1286144},
        {128,  128,  512,  128, 1417216},
        {128,    3,  512,  128, 1482752},
    };

    float* xT = buf + OFF_XT;
    float* h1 = buf + OFF_H1;
    float* h2 = buf + OFF_H2;
    float* h3 = buf + OFF_H3;
    float* h4 = buf + OFF_H4;
    float* h6 = buf + OFF_H6;
    float* h7 = buf + OFF_H7;
    float* h8 = buf + OFF_H8;
    float* h9 = buf + OFF_H9;
    float* meanB = buf + OFF_MEAN;
    float* rstdB = buf + OFF_RSTD;
    float* gf    = buf + OFF_GF;
    float* bias6 = buf + OFF_B6;
    float* ps    = buf + OFF_PS;
    float* pqb   = buf + OFF_PQ;
    float* pm    = buf + OFF_PM;

    cudaFuncSetAttribute(kan_mma, cudaFuncAttributeMaxDynamicSharedMemorySize, S_TOTAL);

    for (int l = 0; l < 10; l++) {
        int tot = L[l].rows * L[l].kp;
        wcvt<<<(tot + 255) / 256, 256>>>(w[l], L[l].cout, L[l].cin, L[l].kp,
                                         L[l].rows, whi + L[l].woff, wlo + L[l].woff);
    }
    xpose<<<(2 * BN_TOT + 255) / 256, 256>>>(x, xT);

    auto M = [&](int s) { return meanB + s * 1024; };
    auto R = [&](int s) { return rstdB + s * 1024; };

    auto gemm = [&](int l, const float* Hin, const float* mn, const float* rs,
                    const float* bias, float* Hout, int wm, int st, int mx) {
        dim3 grid(GX, L[l].rows / 128, 1);
        kan_mma<<<grid, 512, S_TOTAL>>>(Hin, mn, rs, whi + L[l].woff, wlo + L[l].woff,
                                        bias, Hout, ps, pqb, pm,
                                        L[l].cin, L[l].cout, L[l].kp, L[l].kp / 64,
                                        wm, st, mx);
    };
    auto fin = [&](int slot, int C) {
        bn_fin<<<(C + 7) / 8, 256>>>(ps, pqb, M(slot), R(slot), C);
    };

    gemm(0, xT, nullptr, nullptr, nullptr, h1, 0, 1, 0);  fin(0, 64);
    gemm(1, h1, M(0), R(0), nullptr, h2, 0, 1, 0);        fin(1, 64);
    gemm(2, h2, M(1), R(1), nullptr, h3, 0, 1, 0);        fin(2, 64);
    gemm(3, h3, M(2), R(2), nullptr, h4, 0, 1, 0);        fin(3, 128);
    gemm(4, h4, M(3), R(3), nullptr, nullptr, 2, 1, 1);   fin(4, 1024);

    {
        dim3 g(4, BB);
        gf_fin<<<g, 256>>>(pm, M(4), R(4), gf);
    }
    {
        dim3 g(2, BB);
        bias6_kernel<<<g, 256>>>(gf, w[5], bias6);
    }

    gemm(5, h2, M(1), R(1), bias6, h6, 0, 1, 0);          fin(5, 512);
    gemm(6, h6, M(5), R(5), nullptr, h7, 0, 1, 0);        fin(6, 256);
    gemm(7, h7, M(6), R(6), nullptr, h8, 0, 1, 0);        fin(7, 128);
    gemm(8, h8, M(7), R(7), nullptr, h9, 0, 1, 0);        fin(8, 128);
    gemm(9, h9, M(8), R(8), nullptr, (float*)d_out, 1, 0, 0);
}

// round 4
// speedup vs baseline: 2.6160x; 1.1659x over previous
#include <cuda_runtime.h>
#include <cuda_bf16.h>
#include <math.h>
#include <float.h>
#include <stdint.h>

#define BB 32
#define NN 1024
#define BN_TOT 32768
#define GX 256                     /* point tiles = BN/128 */

#define SWZ128(o) ((o) ^ (((o) >> 3) & 0x70))

__device__ __forceinline__ uint32_t smem_u32(const void* p) {
    uint32_t a;
    asm("{ .reg .u64 t; cvta.to.shared.u64 t, %1; cvt.u32.u64 %0, t; }"
        : "=r"(a) : "l"(p));
    return a;
}
__device__ __forceinline__ uint32_t pack_bf2(float lo, float hi) {
    uint32_t r;
    asm("cvt.rn.bf16x2.f32 %0, %1, %2;" : "=r"(r) : "f"(hi), "f"(lo));
    return r;
}
__device__ __forceinline__ void ldm_x4(uint32_t* r, uint32_t addr) {
    asm volatile("ldmatrix.sync.aligned.m8n8.x4.shared.b16 {%0,%1,%2,%3}, [%4];"
                 : "=r"(r[0]), "=r"(r[1]), "=r"(r[2]), "=r"(r[3]) : "r"(addr));
}
__device__ __forceinline__ void mma16816(float* d, const uint32_t* a, const uint32_t* b) {
    asm volatile(
        "mma.sync.aligned.m16n8k16.row.col.f32.bf16.bf16.f32 "
        "{%0,%1,%2,%3}, {%4,%5,%6,%7}, {%8,%9}, {%0,%1,%2,%3};"
        : "+f"(d[0]), "+f"(d[1]), "+f"(d[2]), "+f"(d[3])
        : "r"(a[0]), "r"(a[1]), "r"(a[2]), "r"(a[3]), "r"(b[0]), "r"(b[1]));
}
__device__ __forceinline__ void cp16(uint32_t dst, const void* src) {
    asm volatile("cp.async.cg.shared.global [%0], [%1], 16;" :: "r"(dst), "l"(src));
}
__device__ __forceinline__ void cp_commit() {
    asm volatile("cp.async.commit_group;" ::: "memory");
}
__device__ __forceinline__ void cp_wait0() {
    asm volatile("cp.async.wait_group 0;" ::: "memory");
}

// ===================== scratch =====================
static constexpr size_t CH = (size_t)BN_TOT;
static constexpr size_t OFF_XT = 0;                    // 2 ch
static constexpr size_t OFF_H1 = OFF_XT + 2 * CH;
static constexpr size_t OFF_H2 = OFF_H1 + 64 * CH;
static constexpr size_t OFF_H3 = OFF_H2 + 64 * CH;
static constexpr size_t OFF_H4 = OFF_H3 + 64 * CH;
static constexpr size_t OFF_H6 = OFF_H4 + 128 * CH;    // h5 never materialized
static constexpr size_t OFF_H7 = OFF_H6 + 512 * CH;
static constexpr size_t OFF_H8 = OFF_H7 + 256 * CH;
static constexpr size_t OFF_H9 = OFF_H8 + 128 * CH;
static constexpr size_t OFF_MEAN = OFF_H9 + 128 * CH;  // 10*1024
static constexpr size_t OFF_RSTD = OFF_MEAN + 10 * 1024;
static constexpr size_t OFF_GF   = OFF_RSTD + 10 * 1024;       // 32*1024
static constexpr size_t OFF_B6   = OFF_GF + (size_t)BB * 1024; // 32*512
static constexpr size_t OFF_PS   = OFF_B6 + (size_t)BB * 512;  // 1024*GX
static constexpr size_t OFF_PQ   = OFF_PS + 1024 * (size_t)GX;
static constexpr size_t OFF_PM   = OFF_PQ + 1024 * (size_t)GX;
static constexpr size_t TOTAL_F  = OFF_PM + 1024 * (size_t)GX;

__device__ float g_buf[TOTAL_F];

static constexpr size_t WTOT = 1548288;
__device__ __nv_bfloat16 g_whi[WTOT];
__device__ __nv_bfloat16 g_wlo[WTOT];

// ===================== layer table =====================
struct LayerP { int cin, cout, kp, rows; unsigned woff; };
__constant__ LayerP c_L[10] = {
    {  2,   64,   64,  128,       0},
    { 64,   64,  256,  128,    8192},
    { 64,   64,  256,  128,   40960},
    { 64,  128,  256,  128,   73728},
    {128, 1024,  512, 1024,  106496},
    { 64,  512,  256,  512,  630784},
    {512,  256, 2048,  256,  761856},
    {256,  128, 1024,  128, 1286144},
    {128,  128,  512,  128, 1417216},
    {128,    3,  512,  128, 1482752},
};
struct WPtrs { const float* p[10]; };

// ===================== weight convert (all layers, one launch) ==============
__global__ __launch_bounds__(256) void wcvt_all(
    WPtrs wp, __nv_bfloat16* __restrict__ hi, __nv_bfloat16* __restrict__ lo)
{
    const LayerP L = c_L[blockIdx.y];
    int idx = blockIdx.x * 256 + threadIdx.x;
    if (idx >= L.rows * L.kp) return;
    int r = idx / L.kp, k = idx - r * L.kp;
    int i = k >> 2, d = k & 3;
    float w = 0.0f;
    if (r < L.cout && i < L.cin)
        w = wp.p[blockIdx.y][((size_t)i * L.cout + r) * 4 + d];
    __nv_bfloat16 h = __float2bfloat16(w);
    hi[L.woff + idx] = h;
    lo[L.woff + idx] = __float2bfloat16(w - __bfloat162float(h));
}

// ===================== x (B,2,N) -> xT [2][B*N] =====================
__global__ __launch_bounds__(256) void xpose(const float* __restrict__ x,
                                             float* __restrict__ xT)
{
    int idx = blockIdx.x * 256 + threadIdx.x;
    if (idx >= 2 * BN_TOT) return;
    int c = idx >> 15, bn = idx & (BN_TOT - 1);
    int b = bn >> 10, n = bn & 1023;
    xT[idx] = x[((size_t)b * 2 + c) * NN + n];
}

// ===================== fused featurize + split-bf16 HMMA GEMM ==============
// Double-buffered: WH 16K | WL 16K | FH 16K | FL 16K per stage, 2 stages.
static constexpr int S_WH = 0;
static constexpr int S_WL = 16384;
static constexpr int S_FH = 32768;
static constexpr int S_FL = 49152;
static constexpr int S_STG = 65536;
static constexpr int S_TOTAL = 131072;

__global__ __launch_bounds__(512) void kan_mma(
    const float* __restrict__ Hin, const float* __restrict__ mean,
    const float* __restrict__ rstd,
    const __nv_bfloat16* __restrict__ Whi, const __nv_bfloat16* __restrict__ Wlo,
    const float* __restrict__ bias, float* __restrict__ out,
    float* __restrict__ psum, float* __restrict__ pq, float* __restrict__ pmax,
    int Cin, int Cout, int Kp, int nChunks,
    int writeMode /*0 normal,1 final(B,3,N),2 none*/, int doStats, int doMax)
{
    extern __shared__ __align__(1024) char dsm[];
    const uint32_t sb = smem_u32(dsm);
    const int tid = threadIdx.x;
    const int wid = tid >> 5;
    const int lane = tid & 31;
    const int warpM = wid >> 2;   // 0..3 (32 out rows each)
    const int warpN = wid & 3;    // 0..3 (32 points each)
    const int pBase = blockIdx.x * 128;
    const int oBase = blockIdx.y * 128;
    const bool hasBN = (mean != nullptr);

    float acc[2][4][4];
#pragma unroll
    for (int mt = 0; mt < 2; mt++)
#pragma unroll
        for (int nt = 0; nt < 4; nt++)
#pragma unroll
            for (int e = 0; e < 4; e++) acc[mt][nt][e] = 0.0f;

    const int icl = tid >> 5;     // feature channel (0..15)
    const int pl  = tid & 31;     // point sub-index

    // ---- helpers as lambdas ----
    auto stageW = [&](int kc, int sOff) {
#pragma unroll
        for (int l = 0; l < 2; l++) {
            int idx = tid + l * 512;
            int row = idx >> 3, c16 = idx & 7;
            size_t g = (size_t)(oBase + row) * Kp + (size_t)kc * 64 + c16 * 8;
            uint32_t off = SWZ128(row * 128 + c16 * 16);
            cp16(sb + sOff + S_WH + off, Whi + g);
            cp16(sb + sOff + S_WL + off, Wlo + g);
        }
    };
    float av[4];
    auto prefA = [&](int kc) {
        const int ch = kc * 16 + icl;
        const bool valid = ch < Cin;
        const float* hrow = Hin + (size_t)(valid ? ch : 0) * BN_TOT + pBase;
#pragma unroll
        for (int j = 0; j < 4; j++)
            av[j] = valid ? hrow[pl + 32 * j] : 0.0f;
    };
    auto featStore = [&](int kc, int sOff) {
        const int ch = kc * 16 + icl;
        float mn = 0.f, rs = 1.f;
        if (hasBN && ch < Cin) { mn = mean[ch]; rs = rstd[ch]; }
#pragma unroll
        for (int j = 0; j < 4; j++) {
            const int p = pl + 32 * j;
            float v = hasBN ? (av[j] - mn) * rs : av[j];
            float t = tanhf(v);
            float q1 = 2.0f * t;
            float q2 = 3.75f * t * t - 0.75f;
            float q3 = 1.8666666666666667f * t * q2 - 0.8f * q1;
            uint32_t w01 = pack_bf2(1.0f, q1);
            uint32_t w23 = pack_bf2(q2, q3);
            float h1f = __uint_as_float(w01 & 0xFFFF0000u);
            float h2f = __uint_as_float(w23 << 16);
            float h3f = __uint_as_float(w23 & 0xFFFF0000u);
            uint32_t l01 = pack_bf2(0.0f, q1 - h1f);
            uint32_t l23 = pack_bf2(q2 - h2f, q3 - h3f);
            int o0 = SWZ128(p * 128 + icl * 8);
            *(uint2*)(dsm + sOff + S_FH + o0) = make_uint2(w01, w23);
            *(uint2*)(dsm + sOff + S_FL + o0) = make_uint2(l01, l23);
        }
    };
    auto doMMA = [&](int sOff) {
#pragma unroll
        for (int ks = 0; ks < 4; ks++) {
            uint32_t ah[2][4], al[2][4];
#pragma unroll
            for (int mt = 0; mt < 2; mt++) {
                int r = warpM * 32 + mt * 16 + (lane & 15);
                int cB = ks * 32 + (lane >> 4) * 16;
                uint32_t a = sb + sOff + SWZ128(r * 128 + cB);
                ldm_x4(ah[mt], a + S_WH);
                ldm_x4(al[mt], a + S_WL);
            }
            uint32_t fh[2][4], fl[2][4];
#pragma unroll
            for (int ntp = 0; ntp < 2; ntp++) {
                int rN = warpN * 32 + ntp * 16 + ((lane >> 4) << 3) + (lane & 7);
                int cB = ks * 32 + ((lane >> 3) & 1) * 16;
                uint32_t a = sb + sOff + SWZ128(rN * 128 + cB);
                ldm_x4(fh[ntp], a + S_FH);
                ldm_x4(fl[ntp], a + S_FL);
            }
#pragma unroll
            for (int mt = 0; mt < 2; mt++)
#pragma unroll
                for (int ntp = 0; ntp < 2; ntp++)
#pragma unroll
                    for (int s = 0; s < 2; s++) {
                        int nt = 2 * ntp + s;
                        mma16816(acc[mt][nt], ah[mt], &fh[ntp][2 * s]);
                        mma16816(acc[mt][nt], al[mt], &fh[ntp][2 * s]);
                        mma16816(acc[mt][nt], ah[mt], &fl[ntp][2 * s]);
                    }
        }
    };

    // ---- prologue ----
    stageW(0, 0); cp_commit();
    prefA(0);
    featStore(0, 0);
    cp_wait0();
    __syncthreads();

    // ---- pipelined main loop ----
    for (int kc = 0; kc < nChunks; kc++) {
        const int sOff = (kc & 1) ? S_STG : 0;
        const int nOff = (kc & 1) ? 0 : S_STG;
        const bool more = (kc + 1 < nChunks);
        if (more) {
            stageW(kc + 1, nOff); cp_commit();
            prefA(kc + 1);
        }
        doMMA(sOff);
        if (more) {
            featStore(kc + 1, nOff);
            cp_wait0();
        }
        __syncthreads();
    }

    // ---- epilogue ----
    const int bIdx = pBase >> 10;

#pragma unroll
    for (int mt = 0; mt < 2; mt++)
#pragma unroll
        for (int h = 0; h < 2; h++) {
            int o = oBase + warpM * 32 + mt * 16 + h * 8 + (lane >> 2);
            float bv = 0.f;
            if (bias && o < Cout) bv = bias[bIdx * Cout + o];
            if (bv != 0.f)
#pragma unroll
                for (int nt = 0; nt < 4; nt++) {
                    acc[mt][nt][h * 2 + 0] += bv;
                    acc[mt][nt][h * 2 + 1] += bv;
                }
        }

    if (writeMode == 0) {
#pragma unroll
        for (int mt = 0; mt < 2; mt++)
#pragma unroll
            for (int h = 0; h < 2; h++) {
                int o = oBase + warpM * 32 + mt * 16 + h * 8 + (lane >> 2);
                if (o < Cout) {
                    float* rowp = out + (size_t)o * BN_TOT + pBase;
#pragma unroll
                    for (int nt = 0; nt < 4; nt++) {
                        int p = warpN * 32 + nt * 8 + (lane & 3) * 2;
                        *(float2*)(rowp + p) =
                            make_float2(acc[mt][nt][h * 2], acc[mt][nt][h * 2 + 1]);
                    }
                }
            }
    } else if (writeMode == 1) {
#pragma unroll
        for (int mt = 0; mt < 2; mt++)
#pragma unroll
            for (int h = 0; h < 2; h++) {
                int o = oBase + warpM * 32 + mt * 16 + h * 8 + (lane >> 2);
                if (o < 3) {
                    float* rowp = out + ((size_t)bIdx * 3 + o) * 1024 + (pBase & 1023);
#pragma unroll
                    for (int nt = 0; nt < 4; nt++) {
                        int p = warpN * 32 + nt * 8 + (lane & 3) * 2;
                        rowp[p]     = acc[mt][nt][h * 2];
                        rowp[p + 1] = acc[mt][nt][h * 2 + 1];
                    }
                }
            }
    }

    if (doStats) {
        float* red = (float*)dsm;   // tiles are dead; reuse
#pragma unroll
        for (int mt = 0; mt < 2; mt++)
#pragma unroll
            for (int h = 0; h < 2; h++) {
                float s = 0.f, q = 0.f, mx = -FLT_MAX;
#pragma unroll
                for (int nt = 0; nt < 4; nt++)
#pragma unroll
                    for (int e = 0; e < 2; e++) {
                        float v = acc[mt][nt][h * 2 + e];
                        s += v; q += v * v; mx = fmaxf(mx, v);
                    }
                s += __shfl_xor_sync(~0u, s, 1); s += __shfl_xor_sync(~0u, s, 2);
                q += __shfl_xor_sync(~0u, q, 1); q += __shfl_xor_sync(~0u, q, 2);
                mx = fmaxf(mx, __shfl_xor_sync(~0u, mx, 1));
                mx = fmaxf(mx, __shfl_xor_sync(~0u, mx, 2));
                if ((lane & 3) == 0) {
                    int row = warpM * 32 + mt * 16 + h * 8 + (lane >> 2);
                    red[warpN * 128 + row] = s;
                    red[512 + warpN * 128 + row] = q;
                    if (doMax) red[1024 + warpN * 128 + row] = mx;
                }
            }
        __syncthreads();
        if (tid < 128) {
            float s = 0.f, q = 0.f, mx = -FLT_MAX;
#pragma unroll
            for (int wn = 0; wn < 4; wn++) {
                s += red[wn * 128 + tid];
                q += red[512 + wn * 128 + tid];
                if (doMax) mx = fmaxf(mx, red[1024 + wn * 128 + tid]);
            }
            int o = oBase + tid;
            psum[(size_t)o * GX + blockIdx.x] = s;
            pq[(size_t)o * GX + blockIdx.x] = q;
            if (doMax) pmax[(size_t)o * GX + blockIdx.x] = mx;
        }
    }
}

// ===================== BN finalize: warp per channel =====================
__global__ __launch_bounds__(256) void bn_fin(
    const float* __restrict__ ps, const float* __restrict__ pq,
    float* __restrict__ mean, float* __restrict__ rstd, int C)
{
    int w = threadIdx.x >> 5, lane = threadIdx.x & 31;
    int c = blockIdx.x * 8 + w;
    if (c >= C) return;
    float s = 0.f, q = 0.f;
    for (int j = lane; j < GX; j += 32) {
        s += ps[(size_t)c * GX + j];
        q += pq[(size_t)c * GX + j];
    }
#pragma unroll
    for (int o = 16; o; o >>= 1) {
        s += __shfl_xor_sync(~0u, s, o);
        q += __shfl_xor_sync(~0u, q, o);
    }
    if (lane == 0) {
        float m = s * (1.0f / BN_TOT);
        mean[c] = m;
        rstd[c] = rsqrtf(q * (1.0f / BN_TOT) - m * m + 1e-5f);
    }
}

// ===================== gf finalize: max over 8 point-tiles, then BN =========
__global__ __launch_bounds__(256) void gf_fin(
    const float* __restrict__ pm, const float* __restrict__ mean,
    const float* __restrict__ rstd, float* __restrict__ gf)
{
    int c = blockIdx.x * 256 + threadIdx.x;
    int b = blockIdx.y;
    float mx = -FLT_MAX;
#pragma unroll
    for (int j = 0; j < 8; j++)
        mx = fmaxf(mx, pm[(size_t)c * GX + b * 8 + j]);
    gf[b * 1024 + c] = (mx - mean[c]) * rstd[c];
}

// ===================== fold broadcast gf channels into layer-6 bias ==========
__global__ __launch_bounds__(256) void bias6_kernel(const float* __restrict__ gf,
                                                    const float* __restrict__ W6,
                                                    float* __restrict__ bias6)
{
    const int b = blockIdx.y;
    const int o = blockIdx.x * 256 + threadIdx.x;
    __shared__ float feat[4096];
    for (int idx = threadIdx.x; idx < 1024; idx += 256) {
        float t = tanhf(gf[b * 1024 + idx]);
        float q1 = 2.0f * t;
        float q2 = 3.75f * t * t - 0.75f;
        float q3 = 1.8666666666666667f * t * q2 - 0.8f * q1;
        feat[idx * 4 + 0] = 1.0f;
        feat[idx * 4 + 1] = q1;
        feat[idx * 4 + 2] = q2;
        feat[idx * 4 + 3] = q3;
    }
    __syncthreads();
    float s = 0.f;
    for (int c = 0; c < 1024; c++) {
        float4 w4 = *(const float4*)(W6 + ((size_t)(64 + c) * 512 + o) * 4);
        s += feat[c * 4 + 0] * w4.x + feat[c * 4 + 1] * w4.y +
             feat[c * 4 + 2] * w4.z + feat[c * 4 + 3] * w4.w;
    }
    bias6[b * 512 + o] = s;
}

// ===================== host =====================
static const LayerP h_L[10] = {
    {  2,   64,   64,  128,       0},
    { 64,   64,  256,  128,    8192},
    { 64,   64,  256,  128,   40960},
    { 64,  128,  256,  128,   73728},
    {128, 1024,  512, 1024,  106496},
    { 64,  512,  256,  512,  630784},
    {512,  256, 2048,  256,  761856},
    {256,  128, 1024,  128, 1286144},
    {128,  128,  512,  128, 1417216},
    {128,    3,  512,  128, 1482752},
};

extern "C" void kernel_launch(void* const* d_in, const int* in_sizes, int n_in,
                              void* d_out, int out_size)
{
    (void)in_sizes; (void)n_in; (void)out_size;
    const float* x = (const float*)d_in[0];
    WPtrs wp;
    for (int i = 0; i < 10; i++) wp.p[i] = (const float*)d_in[1 + i];

    float* buf = nullptr;
    cudaGetSymbolAddress((void**)&buf, g_buf);
    __nv_bfloat16* whi = nullptr;
    __nv_bfloat16* wlo = nullptr;
    cudaGetSymbolAddress((void**)&whi, g_whi);
    cudaGetSymbolAddress((void**)&wlo, g_wlo);

    float* xT = buf + OFF_XT;
    float* h1 = buf + OFF_H1;
    float* h2 = buf + OFF_H2;
    float* h3 = buf + OFF_H3;
    float* h4 = buf + OFF_H4;
    float* h6 = buf + OFF_H6;
    float* h7 = buf + OFF_H7;
    float* h8 = buf + OFF_H8;
    float* h9 = buf + OFF_H9;
    float* meanB = buf + OFF_MEAN;
    float* rstdB = buf + OFF_RSTD;
    float* gf    = buf + OFF_GF;
    float* bias6 = buf + OFF_B6;
    float* ps    = buf + OFF_PS;
    float* pqb   = buf + OFF_PQ;
    float* pm    = buf + OFF_PM;

    cudaFuncSetAttribute(kan_mma, cudaFuncAttributeMaxDynamicSharedMemorySize, S_TOTAL);

    {
        dim3 g(2048, 10);
        wcvt_all<<<g, 256>>>(wp, whi, wlo);
    }
    xpose<<<(2 * BN_TOT + 255) / 256, 256>>>(x, xT);

    auto M = [&](int s) { return meanB + s * 1024; };
    auto R = [&](int s) { return rstdB + s * 1024; };

    auto gemm = [&](int l, const float* Hin, const float* mn, const float* rs,
                    const float* bias, float* Hout, int wm, int st, int mx) {
        dim3 grid(GX, h_L[l].rows / 128, 1);
        kan_mma<<<grid, 512, S_TOTAL>>>(Hin, mn, rs, whi + h_L[l].woff, wlo + h_L[l].woff,
                                        bias, Hout, ps, pqb, pm,
                                        h_L[l].cin, h_L[l].cout, h_L[l].kp,
                                        h_L[l].kp / 64, wm, st, mx);
    };
    auto fin = [&](int slot, int C) {
        bn_fin<<<(C + 7) / 8, 256>>>(ps, pqb, M(slot), R(slot), C);
    };

    gemm(0, xT, nullptr, nullptr, nullptr, h1, 0, 1, 0);  fin(0, 64);
    gemm(1, h1, M(0), R(0), nullptr, h2, 0, 1, 0);        fin(1, 64);
    gemm(2, h2, M(1), R(1), nullptr, h3, 0, 1, 0);        fin(2, 64);
    gemm(3, h3, M(2), R(2), nullptr, h4, 0, 1, 0);        fin(3, 128);
    gemm(4, h4, M(3), R(3), nullptr, nullptr, 2, 1, 1);   fin(4, 1024);

    {
        dim3 g(4, BB);
        gf_fin<<<g, 256>>>(pm, M(4), R(4), gf);
    }
    {
        dim3 g(2, BB);
        bias6_kernel<<<g, 256>>>(gf, wp.p[5], bias6);
    }

    gemm(5, h2, M(1), R(1), bias6, h6, 0, 1, 0);          fin(5, 512);
    gemm(6, h6, M(5), R(5), nullptr, h7, 0, 1, 0);        fin(6, 256);
    gemm(7, h7, M(6), R(6), nullptr, h8, 0, 1, 0);        fin(7, 128);
    gemm(8, h8, M(7), R(7), nullptr, h9, 0, 1, 0);        fin(8, 128);
    gemm(9, h9, M(8), R(8), nullptr, (float*)d_out, 1, 0, 0);
}

// round 5
// speedup vs baseline: 2.6827x; 1.0255x over previous
#include <cuda_runtime.h>
#include <cuda_bf16.h>
#include <math.h>
#include <float.h>
#include <stdint.h>

#define BB 32
#define NN 1024
#define BN_TOT 32768
#define GXMAX 256

#define SWZ128(o) ((o) ^ (((o) >> 3) & 0x70))

__device__ __forceinline__ uint32_t smem_u32(const void* p) {
    uint32_t a;
    asm("{ .reg .u64 t; cvta.to.shared.u64 t, %1; cvt.u32.u64 %0, t; }"
        : "=r"(a) : "l"(p));
    return a;
}
__device__ __forceinline__ uint32_t pack_bf2(float lo, float hi) {
    uint32_t r;
    asm("cvt.rn.bf16x2.f32 %0, %1, %2;" : "=r"(r) : "f"(hi), "f"(lo));
    return r;
}
__device__ __forceinline__ void ldm_x4(uint32_t* r, uint32_t addr) {
    asm volatile("ldmatrix.sync.aligned.m8n8.x4.shared.b16 {%0,%1,%2,%3}, [%4];"
                 : "=r"(r[0]), "=r"(r[1]), "=r"(r[2]), "=r"(r[3]) : "r"(addr));
}
__device__ __forceinline__ void mma16816(float* d, const uint32_t* a, const uint32_t* b) {
    asm volatile(
        "mma.sync.aligned.m16n8k16.row.col.f32.bf16.bf16.f32 "
        "{%0,%1,%2,%3}, {%4,%5,%6,%7}, {%8,%9}, {%0,%1,%2,%3};"
        : "+f"(d[0]), "+f"(d[1]), "+f"(d[2]), "+f"(d[3])
        : "r"(a[0]), "r"(a[1]), "r"(a[2]), "r"(a[3]), "r"(b[0]), "r"(b[1]));
}
__device__ __forceinline__ void cp16(uint32_t dst, const void* src) {
    asm volatile("cp.async.cg.shared.global [%0], [%1], 16;" :: "r"(dst), "l"(src));
}
__device__ __forceinline__ void cp_commit() {
    asm volatile("cp.async.commit_group;" ::: "memory");
}
__device__ __forceinline__ void cp_wait0() {
    asm volatile("cp.async.wait_group 0;" ::: "memory");
}

// ===================== scratch =====================
static constexpr size_t CH = (size_t)BN_TOT;
static constexpr size_t OFF_H1 = 0;
static constexpr size_t OFF_H2 = OFF_H1 + 64 * CH;
static constexpr size_t OFF_H3 = OFF_H2 + 64 * CH;
static constexpr size_t OFF_H4 = OFF_H3 + 64 * CH;
static constexpr size_t OFF_H6 = OFF_H4 + 128 * CH;    // h5 never materialized
static constexpr size_t OFF_H7 = OFF_H6 + 512 * CH;
static constexpr size_t OFF_H8 = OFF_H7 + 256 * CH;
static constexpr size_t OFF_H9 = OFF_H8 + 128 * CH;
static constexpr size_t OFF_MEAN = OFF_H9 + 128 * CH;
static constexpr size_t OFF_RSTD = OFF_MEAN + 10 * 1024;
static constexpr size_t OFF_B6   = OFF_RSTD + 10 * 1024;       // 32*512
static constexpr size_t OFF_PS   = OFF_B6 + (size_t)BB * 512;  // 1024*GXMAX
static constexpr size_t OFF_PQ   = OFF_PS + 1024 * (size_t)GXMAX;
static constexpr size_t OFF_PM   = OFF_PQ + 1024 * (size_t)GXMAX;
static constexpr size_t TOTAL_F  = OFF_PM + 1024 * (size_t)GXMAX;

__device__ float g_buf[TOTAL_F];

static constexpr size_t WTOT = 1548288;
__device__ __nv_bfloat16 g_whi[WTOT];
__device__ __nv_bfloat16 g_wlo[WTOT];

// ===================== layer table =====================
struct LayerP { int cin, cout, kp, rows; unsigned woff; };
__constant__ LayerP c_L[10] = {
    {  2,   64,   64,  128,       0},
    { 64,   64,  256,  128,    8192},
    { 64,   64,  256,  128,   40960},
    { 64,  128,  256,  128,   73728},
    {128, 1024,  512, 1024,  106496},
    { 64,  512,  256,  512,  630784},
    {512,  256, 2048,  256,  761856},
    {256,  128, 1024,  128, 1286144},
    {128,  128,  512,  128, 1417216},
    {128,    3,  512,  128, 1482752},
};
struct WPtrs { const float* p[10]; };

// ===================== weight convert (all layers, one launch) ==============
__global__ __launch_bounds__(256) void wcvt_all(
    WPtrs wp, __nv_bfloat16* __restrict__ hi, __nv_bfloat16* __restrict__ lo)
{
    const LayerP L = c_L[blockIdx.y];
    int idx = blockIdx.x * 256 + threadIdx.x;
    if (idx >= L.rows * L.kp) return;
    int r = idx / L.kp, k = idx - r * L.kp;
    int i = k >> 2, d = k & 3;
    float w = 0.0f;
    if (r < L.cout && i < L.cin)
        w = wp.p[blockIdx.y][((size_t)i * L.cout + r) * 4 + d];
    __nv_bfloat16 h = __float2bfloat16(w);
    hi[L.woff + idx] = h;
    lo[L.woff + idx] = __float2bfloat16(w - __bfloat162float(h));
}

// ===================== fused featurize + split-bf16 HMMA GEMM ==============
template <int NT>
__global__ __launch_bounds__(512) void kan_mma(
    const float* __restrict__ Hin, const float* __restrict__ mean,
    const float* __restrict__ rstd,
    const __nv_bfloat16* __restrict__ Whi, const __nv_bfloat16* __restrict__ Wlo,
    const float* __restrict__ bias, float* __restrict__ out,
    float* __restrict__ psum, float* __restrict__ pq, float* __restrict__ pmax,
    int Cin, int Cout, int Kp, int nChunks,
    int writeMode /*0 normal,1 final,2 none*/, int doStats, int doMax,
    int inBatched)
{
    constexpr int S_WH = 0;
    constexpr int S_WL = 16384;
    constexpr int S_FH = 32768;
    constexpr int S_FL = 32768 + NT * 128;
    constexpr int S_STG = 32768 + 2 * NT * 128;
    constexpr int NTW = NT / 4;       // points per warpN
    constexpr int NTP = NT / 64;      // ldm feature groups per warpN
    constexpr int NJ = NT / 32;       // points per producer thread

    extern __shared__ __align__(1024) char dsm[];
    const uint32_t sb = smem_u32(dsm);
    const int tid = threadIdx.x;
    const int wid = tid >> 5;
    const int lane = tid & 31;
    const int warpM = wid >> 2;
    const int warpN = wid & 3;
    const int pBase = blockIdx.x * NT;
    const int oBase = blockIdx.y * 128;
    const int bIdx = pBase >> 10;
    const bool hasBN = (mean != nullptr);

    float acc[2][2 * NTP][4];
#pragma unroll
    for (int mt = 0; mt < 2; mt++)
#pragma unroll
        for (int nt = 0; nt < 2 * NTP; nt++)
#pragma unroll
            for (int e = 0; e < 4; e++) acc[mt][nt][e] = 0.0f;

    const int icl = tid >> 5;
    const int pl  = tid & 31;

    auto stageW = [&](int kc, int sOff) {
#pragma unroll
        for (int l = 0; l < 2; l++) {
            int idx = tid + l * 512;
            int row = idx >> 3, c16 = idx & 7;
            size_t g = (size_t)(oBase + row) * Kp + (size_t)kc * 64 + c16 * 8;
            uint32_t off = SWZ128(row * 128 + c16 * 16);
            cp16(sb + sOff + S_WH + off, Whi + g);
            cp16(sb + sOff + S_WL + off, Wlo + g);
        }
    };
    float av[NJ];
    auto prefA = [&](int kc) {
        const int ch = kc * 16 + icl;
        const bool valid = ch < Cin;
        const float* hrow;
        if (inBatched)
            hrow = Hin + ((size_t)bIdx * Cin + (valid ? ch : 0)) * NN + (pBase & 1023);
        else
            hrow = Hin + (size_t)(valid ? ch : 0) * BN_TOT + pBase;
#pragma unroll
        for (int j = 0; j < NJ; j++)
            av[j] = valid ? hrow[pl + 32 * j] : 0.0f;
    };
    auto featStore = [&](int kc, int sOff) {
        const int ch = kc * 16 + icl;
        float mn = 0.f, rs = 1.f;
        if (hasBN && ch < Cin) { mn = mean[ch]; rs = rstd[ch]; }
#pragma unroll
        for (int j = 0; j < NJ; j++) {
            const int p = pl + 32 * j;
            float v = hasBN ? (av[j] - mn) * rs : av[j];
            float t = tanhf(v);
            float q1 = 2.0f * t;
            float q2 = 3.75f * t * t - 0.75f;
            float q3 = 1.8666666666666667f * t * q2 - 0.8f * q1;
            uint32_t w01 = pack_bf2(1.0f, q1);
            uint32_t w23 = pack_bf2(q2, q3);
            float h1f = __uint_as_float(w01 & 0xFFFF0000u);
            float h2f = __uint_as_float(w23 << 16);
            float h3f = __uint_as_float(w23 & 0xFFFF0000u);
            uint32_t l01 = pack_bf2(0.0f, q1 - h1f);
            uint32_t l23 = pack_bf2(q2 - h2f, q3 - h3f);
            int o0 = SWZ128(p * 128 + icl * 8);
            *(uint2*)(dsm + sOff + S_FH + o0) = make_uint2(w01, w23);
            *(uint2*)(dsm + sOff + S_FL + o0) = make_uint2(l01, l23);
        }
    };
    auto doMMA = [&](int sOff) {
#pragma unroll
        for (int ks = 0; ks < 4; ks++) {
            uint32_t ah[2][4], al[2][4];
#pragma unroll
            for (int mt = 0; mt < 2; mt++) {
                int r = warpM * 32 + mt * 16 + (lane & 15);
                int cB = ks * 32 + (lane >> 4) * 16;
                uint32_t a = sb + sOff + SWZ128(r * 128 + cB);
                ldm_x4(ah[mt], a + S_WH);
                ldm_x4(al[mt], a + S_WL);
            }
#pragma unroll
            for (int ntp = 0; ntp < NTP; ntp++) {
                uint32_t fh[4], fl[4];
                int rN = warpN * NTW + ntp * 16 + ((lane >> 4) << 3) + (lane & 7);
                int cB = ks * 32 + ((lane >> 3) & 1) * 16;
                uint32_t a = sb + sOff + SWZ128(rN * 128 + cB);
                ldm_x4(fh, a + S_FH);
                ldm_x4(fl, a + S_FL);
#pragma unroll
                for (int mt = 0; mt < 2; mt++)
#pragma unroll
                    for (int s = 0; s < 2; s++) {
                        int nt = 2 * ntp + s;
                        mma16816(acc[mt][nt], ah[mt], &fh[2 * s]);
                        mma16816(acc[mt][nt], al[mt], &fh[2 * s]);
                        mma16816(acc[mt][nt], ah[mt], &fl[2 * s]);
                    }
            }
        }
    };

    // ---- prologue ----
    stageW(0, 0); cp_commit();
    prefA(0);
    featStore(0, 0);
    cp_wait0();
    __syncthreads();

    // ---- pipelined main loop ----
    for (int kc = 0; kc < nChunks; kc++) {
        const int sOff = (kc & 1) ? S_STG : 0;
        const int nOff = (kc & 1) ? 0 : S_STG;
        const bool more = (kc + 1 < nChunks);
        if (more) {
            stageW(kc + 1, nOff); cp_commit();
            prefA(kc + 1);
        }
        doMMA(sOff);
        if (more) {
            featStore(kc + 1, nOff);
            cp_wait0();
        }
        __syncthreads();
    }

    // ---- epilogue ----
#pragma unroll
    for (int mt = 0; mt < 2; mt++)
#pragma unroll
        for (int h = 0; h < 2; h++) {
            int o = oBase + warpM * 32 + mt * 16 + h * 8 + (lane >> 2);
            float bv = 0.f;
            if (bias && o < Cout) bv = bias[bIdx * Cout + o];
            if (bv != 0.f)
#pragma unroll
                for (int nt = 0; nt < 2 * NTP; nt++) {
                    acc[mt][nt][h * 2 + 0] += bv;
                    acc[mt][nt][h * 2 + 1] += bv;
                }
        }

    if (writeMode == 0) {
#pragma unroll
        for (int mt = 0; mt < 2; mt++)
#pragma unroll
            for (int h = 0; h < 2; h++) {
                int o = oBase + warpM * 32 + mt * 16 + h * 8 + (lane >> 2);
                if (o < Cout) {
                    float* rowp = out + (size_t)o * BN_TOT + pBase;
#pragma unroll
                    for (int nt = 0; nt < 2 * NTP; nt++) {
                        int p = warpN * NTW + nt * 8 + (lane & 3) * 2;
                        *(float2*)(rowp + p) =
                            make_float2(acc[mt][nt][h * 2], acc[mt][nt][h * 2 + 1]);
                    }
                }
            }
    } else if (writeMode == 1) {
#pragma unroll
        for (int mt = 0; mt < 2; mt++)
#pragma unroll
            for (int h = 0; h < 2; h++) {
                int o = oBase + warpM * 32 + mt * 16 + h * 8 + (lane >> 2);
                if (o < 3) {
                    float* rowp = out + ((size_t)bIdx * 3 + o) * 1024 + (pBase & 1023);
#pragma unroll
                    for (int nt = 0; nt < 2 * NTP; nt++) {
                        int p = warpN * NTW + nt * 8 + (lane & 3) * 2;
                        rowp[p]     = acc[mt][nt][h * 2];
                        rowp[p + 1] = acc[mt][nt][h * 2 + 1];
                    }
                }
            }
    }

    if (doStats) {
        float* red = (float*)dsm;
#pragma unroll
        for (int mt = 0; mt < 2; mt++)
#pragma unroll
            for (int h = 0; h < 2; h++) {
                float s = 0.f, q = 0.f, mx = -FLT_MAX;
#pragma unroll
                for (int nt = 0; nt < 2 * NTP; nt++)
#pragma unroll
                    for (int e = 0; e < 2; e++) {
                        float v = acc[mt][nt][h * 2 + e];
                        s += v; q += v * v; mx = fmaxf(mx, v);
                    }
                s += __shfl_xor_sync(~0u, s, 1); s += __shfl_xor_sync(~0u, s, 2);
                q += __shfl_xor_sync(~0u, q, 1); q += __shfl_xor_sync(~0u, q, 2);
                mx = fmaxf(mx, __shfl_xor_sync(~0u, mx, 1));
                mx = fmaxf(mx, __shfl_xor_sync(~0u, mx, 2));
                if ((lane & 3) == 0) {
                    int row = warpM * 32 + mt * 16 + h * 8 + (lane >> 2);
                    red[warpN * 128 + row] = s;
                    red[512 + warpN * 128 + row] = q;
                    if (doMax) red[1024 + warpN * 128 + row] = mx;
                }
            }
        __syncthreads();
        if (tid < 128) {
            float s = 0.f, q = 0.f, mx = -FLT_MAX;
#pragma unroll
            for (int wn = 0; wn < 4; wn++) {
                s += red[wn * 128 + tid];
                q += red[512 + wn * 128 + tid];
                if (doMax) mx = fmaxf(mx, red[1024 + wn * 128 + tid]);
            }
            int o = oBase + tid;
            psum[(size_t)o * GXMAX + blockIdx.x] = s;
            pq[(size_t)o * GXMAX + blockIdx.x] = q;
            if (doMax) pmax[(size_t)o * GXMAX + blockIdx.x] = mx;
        }
    }
}

// ===================== BN finalize: warp per channel =====================
__global__ __launch_bounds__(256) void bn_fin(
    const float* __restrict__ ps, const float* __restrict__ pq,
    float* __restrict__ mean, float* __restrict__ rstd, int C, int gx)
{
    int w = threadIdx.x >> 5, lane = threadIdx.x & 31;
    int c = blockIdx.x * 8 + w;
    if (c >= C) return;
    float s = 0.f, q = 0.f;
    for (int j = lane; j < gx; j += 32) {
        s += ps[(size_t)c * GXMAX + j];
        q += pq[(size_t)c * GXMAX + j];
    }
#pragma unroll
    for (int o = 16; o; o >>= 1) {
        s += __shfl_xor_sync(~0u, s, o);
        q += __shfl_xor_sync(~0u, q, o);
    }
    if (lane == 0) {
        float m = s * (1.0f / BN_TOT);
        mean[c] = m;
        rstd[c] = rsqrtf(q * (1.0f / BN_TOT) - m * m + 1e-5f);
    }
}

// ============ merged: gf (max over 4 tiles + BN) + bias6 fold ============
__global__ __launch_bounds__(256) void gfbias6(
    const float* __restrict__ pm, const float* __restrict__ mean,
    const float* __restrict__ rstd, const float* __restrict__ W6,
    float* __restrict__ bias6)
{
    const int b = blockIdx.y;
    __shared__ float feat[4096];
    for (int c = threadIdx.x; c < 1024; c += 256) {
        float mx = -FLT_MAX;
#pragma unroll
        for (int j = 0; j < 4; j++)   // L5 uses NT=256 -> 4 tiles per batch
            mx = fmaxf(mx, pm[(size_t)c * GXMAX + b * 4 + j]);
        float g = (mx - mean[c]) * rstd[c];
        float t = tanhf(g);
        float q1 = 2.0f * t;
        float q2 = 3.75f * t * t - 0.75f;
        float q3 = 1.8666666666666667f * t * q2 - 0.8f * q1;
        feat[c * 4 + 0] = 1.0f;
        feat[c * 4 + 1] = q1;
        feat[c * 4 + 2] = q2;
        feat[c * 4 + 3] = q3;
    }
    __syncthreads();
    const int o = blockIdx.x * 256 + threadIdx.x;
    float s = 0.f;
    for (int c = 0; c < 1024; c++) {
        float4 w4 = *(const float4*)(W6 + ((size_t)(64 + c) * 512 + o) * 4);
        s += feat[c * 4 + 0] * w4.x + feat[c * 4 + 1] * w4.y +
             feat[c * 4 + 2] * w4.z + feat[c * 4 + 3] * w4.w;
    }
    bias6[b * 512 + o] = s;
}

// ===================== host =====================
static const LayerP h_L[10] = {
    {  2,   64,   64,  128,       0},
    { 64,   64,  256,  128,    8192},
    { 64,   64,  256,  128,   40960},
    { 64,  128,  256,  128,   73728},
    {128, 1024,  512, 1024,  106496},
    { 64,  512,  256,  512,  630784},
    {512,  256, 2048,  256,  761856},
    {256,  128, 1024,  128, 1286144},
    {128,  128,  512,  128, 1417216},
    {128,    3,  512,  128, 1482752},
};

extern "C" void kernel_launch(void* const* d_in, const int* in_sizes, int n_in,
                              void* d_out, int out_size)
{
    (void)in_sizes; (void)n_in; (void)out_size;
    const float* x = (const float*)d_in[0];
    WPtrs wp;
    for (int i = 0; i < 10; i++) wp.p[i] = (const float*)d_in[1 + i];

    float* buf = nullptr;
    cudaGetSymbolAddress((void**)&buf, g_buf);
    __nv_bfloat16* whi = nullptr;
    __nv_bfloat16* wlo = nullptr;
    cudaGetSymbolAddress((void**)&whi, g_whi);
    cudaGetSymbolAddress((void**)&wlo, g_wlo);

    float* h1 = buf + OFF_H1;
    float* h2 = buf + OFF_H2;
    float* h3 = buf + OFF_H3;
    float* h4 = buf + OFF_H4;
    float* h6 = buf + OFF_H6;
    float* h7 = buf + OFF_H7;
    float* h8 = buf + OFF_H8;
    float* h9 = buf + OFF_H9;
    float* meanB = buf + OFF_MEAN;
    float* rstdB = buf + OFF_RSTD;
    float* bias6 = buf + OFF_B6;
    float* ps    = buf + OFF_PS;
    float* pqb   = buf + OFF_PQ;
    float* pm    = buf + OFF_PM;

    cudaFuncSetAttribute(kan_mma<128>, cudaFuncAttributeMaxDynamicSharedMemorySize, 131072);
    cudaFuncSetAttribute(kan_mma<256>, cudaFuncAttributeMaxDynamicSharedMemorySize, 196608);

    {
        dim3 g(2048, 10);
        wcvt_all<<<g, 256>>>(wp, whi, wlo);
    }

    auto M = [&](int s) { return meanB + s * 1024; };
    auto R = [&](int s) { return rstdB + s * 1024; };

    auto g128 = [&](int l, const float* Hin, const float* mn, const float* rs,
                    const float* bias, float* Hout, int wm, int st, int mx, int ib) {
        dim3 grid(BN_TOT / 128, h_L[l].rows / 128, 1);
        kan_mma<128><<<grid, 512, 131072>>>(Hin, mn, rs, whi + h_L[l].woff,
            wlo + h_L[l].woff, bias, Hout, ps, pqb, pm,
            h_L[l].cin, h_L[l].cout, h_L[l].kp, h_L[l].kp / 64, wm, st, mx, ib);
    };
    auto g256 = [&](int l, const float* Hin, const float* mn, const float* rs,
                    const float* bias, float* Hout, int wm, int st, int mx) {
        dim3 grid(BN_TOT / 256, h_L[l].rows / 128, 1);
        kan_mma<256><<<grid, 512, 196608>>>(Hin, mn, rs, whi + h_L[l].woff,
            wlo + h_L[l].woff, bias, Hout, ps, pqb, pm,
            h_L[l].cin, h_L[l].cout, h_L[l].kp, h_L[l].kp / 64, wm, st, mx, 0);
    };
    auto fin = [&](int slot, int C, int gx) {
        bn_fin<<<(C + 7) / 8, 256>>>(ps, pqb, M(slot), R(slot), C, gx);
    };

    g128(0, x, nullptr, nullptr, nullptr, h1, 0, 1, 0, 1);  fin(0, 64, 256);
    g128(1, h1, M(0), R(0), nullptr, h2, 0, 1, 0, 0);       fin(1, 64, 256);
    g128(2, h2, M(1), R(1), nullptr, h3, 0, 1, 0, 0);       fin(2, 64, 256);
    g128(3, h3, M(2), R(2), nullptr, h4, 0, 1, 0, 0);       fin(3, 128, 256);
    g256(4, h4, M(3), R(3), nullptr, nullptr, 2, 1, 1);     fin(4, 1024, 128);

    {
        dim3 g(2, BB);
        gfbias6<<<g, 256>>>(pm, M(4), R(4), wp.p[5], bias6);
    }

    g256(5, h2, M(1), R(1), bias6, h6, 0, 1, 0);            fin(5, 512, 128);
    g256(6, h6, M(5), R(5), nullptr, h7, 0, 1, 0);          fin(6, 256, 128);
    g128(7, h7, M(6), R(6), nullptr, h8, 0, 1, 0, 0);       fin(7, 128, 256);
    g128(8, h8, M(7), R(7), nullptr, h9, 0, 1, 0, 0);       fin(8, 128, 256);
    g128(9, h9, M(8), R(8), nullptr, (float*)d_out, 1, 0, 0, 0);
}